// round 8
// baseline (speedup 1.0000x reference)
#include <cuda_runtime.h>
#include <math_constants.h>

// Problem shape (fixed by the benchmark)
#define BB   16
#define KC   5
#define NP   4096
#define DD   1024
#define KNN  9

#define BLK_X 32               // sims blocks per batch (32*16 = 512, one wave @6/SM)
#define RPG   4                // rows per unit
#define NWARP 4                // warps per sims block (128 threads)
#define UPW   8                // unit iterations per warp (4 warps*8*4 rows = 128 rows)
#define ROWS_PER_BLK 128
#define NCAND (BLK_X * KNN)    // 288 candidates per (b,k)

// -------- scratch (no device allocation allowed -> __device__ globals) ------
__device__ float2 g_cand[BB * KC * NCAND];  // (val, idx-as-float-bits) 184 KB
__device__ float  g_invnorm[BB * NP];       // 1/||patch||             256 KB

// ============================================================================
// Kernel 1: one pass over patches (268 MB streamed once -> memory bound) PLUS
// first-level top-9. Cue used RAW (positive row-scalar -> same top-9 set; the
// output only involves normalized patches).
// 128 threads + launch_bounds(128,6): reg cap 85 -> RPG=4 fits WITHOUT spills
// at 24 warps/SM. RPG=4 halves smem-crossbar traffic vs RPG=2 (5 LDS per
// 4 LDG instead of per 2), keeping the LDS stream out of the DRAM stream's way.
// ============================================================================
__global__ void __launch_bounds__(128, 6) sims_kernel(const float* __restrict__ patches,
                                                      const float* __restrict__ cue) {
    const int b = blockIdx.y;
    const int bx = blockIdx.x;

    __shared__ float4 s_cue[KC * DD / 4];        // 20 KB (raw cue)
    __shared__ float  s_s[KC][ROWS_PER_BLK];     // 2.5 KB block-local cosines
    {
        const float4* src = (const float4*)(cue + (size_t)b * KC * DD);
        for (int i = threadIdx.x; i < KC * DD / 4; i += 128) s_cue[i] = src[i];
    }
    __syncthreads();

    const int warp = threadIdx.x >> 5;
    const int lane = threadIdx.x & 31;
    const float4* pbase = (const float4*)(patches + (size_t)b * NP * DD);
    const int u0 = bx * (ROWS_PER_BLK / RPG);    // first unit of this block (32 units)

    // warp handles local units warp + m*NWARP, m = 0..7 (depth-1 prefetch)
    const float4* p = pbase + (size_t)(u0 + warp) * RPG * (DD / 4);
    float4 v[RPG], vn[RPG];
    #pragma unroll
    for (int rr = 0; rr < RPG; rr++)
        v[rr] = __ldcs(&p[lane + rr * (DD / 4)]);

    for (int m = 0; m < UPW; m++) {
        const bool has_next = (m < UPW - 1);
        const float4* pn = p + NWARP * RPG * (DD / 4);   // next unit (stride 4 units)

        float acc[RPG][6];
        #pragma unroll
        for (int rr = 0; rr < RPG; rr++)
            #pragma unroll
            for (int i = 0; i < 6; i++) acc[rr][i] = 0.f;

        #pragma unroll
        for (int j = 0; j < 8; j++) {
            // prefetch next chunk (this unit) or first chunk (next unit)
            if (j < 7) {
                const int offn = lane + (j + 1) * 32;
                #pragma unroll
                for (int rr = 0; rr < RPG; rr++)
                    vn[rr] = __ldcs(&p[offn + rr * (DD / 4)]);
            } else if (has_next) {
                #pragma unroll
                for (int rr = 0; rr < RPG; rr++)
                    vn[rr] = __ldcs(&pn[lane + rr * (DD / 4)]);
            }

            const int off = lane + j * 32;               // 256 float4 per row
            #pragma unroll
            for (int rr = 0; rr < RPG; rr++) {
                acc[rr][5] = fmaf(v[rr].x, v[rr].x, acc[rr][5]);
                acc[rr][5] = fmaf(v[rr].y, v[rr].y, acc[rr][5]);
                acc[rr][5] = fmaf(v[rr].z, v[rr].z, acc[rr][5]);
                acc[rr][5] = fmaf(v[rr].w, v[rr].w, acc[rr][5]);
            }
            #pragma unroll
            for (int k = 0; k < KC; k++) {
                const float4 c = s_cue[k * (DD / 4) + off];
                #pragma unroll
                for (int rr = 0; rr < RPG; rr++) {
                    acc[rr][k] = fmaf(v[rr].x, c.x, acc[rr][k]);
                    acc[rr][k] = fmaf(v[rr].y, c.y, acc[rr][k]);
                    acc[rr][k] = fmaf(v[rr].z, c.z, acc[rr][k]);
                    acc[rr][k] = fmaf(v[rr].w, c.w, acc[rr][k]);
                }
            }
            #pragma unroll
            for (int rr = 0; rr < RPG; rr++) v[rr] = vn[rr];
        }

        // epilogue: butterfly -> all lanes hold sums; stage cosines in smem
        const int lrow0 = (warp + m * NWARP) * RPG;      // local row base 0..127
        #pragma unroll
        for (int rr = 0; rr < RPG; rr++) {
            #pragma unroll
            for (int i = 0; i < 6; i++)
                #pragma unroll
                for (int o = 16; o; o >>= 1)
                    acc[rr][i] += __shfl_xor_sync(0xffffffffu, acc[rr][i], o);
            const float inv = rsqrtf(fmaxf(acc[rr][5], 1e-24f));
            float val = acc[rr][0];
            if (lane == 1) val = acc[rr][1];
            if (lane == 2) val = acc[rr][2];
            if (lane == 3) val = acc[rr][3];
            if (lane == 4) val = acc[rr][4];
            if (lane < 5)
                s_s[lane][lrow0 + rr] = val * inv;
            else if (lane == 5)
                g_invnorm[(size_t)b * NP + bx * ROWS_PER_BLK + lrow0 + rr] = inv;
        }

        if (has_next) p = pn;
    }
    __syncthreads();

    // Block-local top-9 per cue. 4 warps: warp w -> cue w; warp 0 also cue 4.
    #pragma unroll
    for (int pass = 0; pass < 2; pass++) {
        const int k = (pass == 0) ? warp : 4;
        if (pass == 1 && warp != 0) break;

        float v4[4];
        const int base = lane * 4;
        #pragma unroll
        for (int i = 0; i < 4; i++) v4[i] = s_s[k][base + i];

        float2* cand = g_cand + ((size_t)(b * KC + k) * BLK_X + bx) * KNN;
        for (int it = 0; it < KNN; it++) {
            float bv = -CUDART_INF_F; int bi = ROWS_PER_BLK;
            #pragma unroll
            for (int i = 0; i < 4; i++)
                if (v4[i] > bv) { bv = v4[i]; bi = base + i; }   // lowest idx on tie
            #pragma unroll
            for (int o = 16; o; o >>= 1) {
                const float ov = __shfl_xor_sync(0xffffffffu, bv, o);
                const int   oi = __shfl_xor_sync(0xffffffffu, bi, o);
                if (ov > bv || (ov == bv && oi < bi)) { bv = ov; bi = oi; }
            }
            if ((bi >> 2) == lane) v4[bi & 3] = -CUDART_INF_F;   // mask winner
            if (lane == 0)
                cand[it] = make_float2(bv, __int_as_float(bx * ROWS_PER_BLK + bi));
        }
    }
}

// ============================================================================
// Kernel 2: merge 288 candidates per (b,k) -> global top-9, then mean of the
// 9 normalized patch rows. grid = 80 blocks, 256 threads.
// ============================================================================
__global__ void __launch_bounds__(256) topk_kernel(const float* __restrict__ patches,
                                                   float* __restrict__ out) {
    const int bk = blockIdx.x;          // 0..79
    const int b = bk / KC;
    const int tid = threadIdx.x;

    __shared__ float s_v[NCAND];
    __shared__ int   s_i[NCAND];
    __shared__ int   s_top[KNN];
    __shared__ float s_inv[KNN];

    const float2* cand = g_cand + (size_t)bk * NCAND;
    for (int t = tid; t < NCAND; t += 256) {
        const float2 c = cand[t];
        s_v[t] = c.x;
        s_i[t] = __float_as_int(c.y);
    }
    __syncthreads();

    if (tid < 32) {
        const int lane = tid;
        // lane holds slots lane + s*32, s = 0..8 (register resident)
        float v[9]; int x[9];
        #pragma unroll
        for (int s = 0; s < 9; s++) {
            const int g = lane + s * 32;
            v[s] = s_v[g]; x[s] = s_i[g];
        }
        for (int it = 0; it < KNN; it++) {
            float bv = -CUDART_INF_F; int bi = NP; int bs = 0;
            #pragma unroll
            for (int s = 0; s < 9; s++)
                if (v[s] > bv || (v[s] == bv && x[s] < bi)) { bv = v[s]; bi = x[s]; bs = s; }
            int blane = lane;
            #pragma unroll
            for (int o = 16; o; o >>= 1) {
                const float ov = __shfl_xor_sync(0xffffffffu, bv, o);
                const int   oi = __shfl_xor_sync(0xffffffffu, bi, o);
                const int   os = __shfl_xor_sync(0xffffffffu, bs, o);
                const int   ol = __shfl_xor_sync(0xffffffffu, blane, o);
                if (ov > bv || (ov == bv && oi < bi)) { bv = ov; bi = oi; bs = os; blane = ol; }
            }
            if (lane == blane) v[bs] = -CUDART_INF_F;          // mask winner
            if (lane == 0) s_top[it] = bi;
        }
    }
    __syncthreads();

    if (tid < KNN)
        s_inv[tid] = g_invnorm[(size_t)b * NP + s_top[tid]];
    __syncthreads();

    // each thread owns one float4 of the D=1024 output
    float4 acc = make_float4(0.f, 0.f, 0.f, 0.f);
    #pragma unroll
    for (int i = 0; i < KNN; i++) {
        const float4* prow =
            (const float4*)(patches + ((size_t)b * NP + s_top[i]) * DD);
        const float4 v = prow[tid];
        const float inv = s_inv[i];
        acc.x += v.x * inv;
        acc.y += v.y * inv;
        acc.z += v.z * inv;
        acc.w += v.w * inv;
    }
    const float sc = 1.0f / (float)KNN;
    float4 o4 = make_float4(acc.x * sc, acc.y * sc, acc.z * sc, acc.w * sc);
    ((float4*)out)[(size_t)bk * (DD / 4) + tid] = o4;
}

// ============================================================================
extern "C" void kernel_launch(void* const* d_in, const int* in_sizes, int n_in,
                              void* d_out, int out_size) {
    const float* cue     = (const float*)d_in[0];
    const float* patches = (const float*)d_in[1];
    // defensive: identify by element count (cue = 81920, patches = 67108864)
    if (n_in >= 2 && in_sizes[0] > in_sizes[1]) {
        cue     = (const float*)d_in[1];
        patches = (const float*)d_in[0];
    }

    dim3 g1(BLK_X, BB);
    sims_kernel<<<g1, 128>>>(patches, cue);

    topk_kernel<<<BB * KC, 256>>>(patches, (float*)d_out);
}

// round 9
// speedup vs baseline: 1.0128x; 1.0128x over previous
#include <cuda_runtime.h>
#include <math_constants.h>

// Problem shape (fixed by the benchmark)
#define BB   16
#define KC   5
#define NP   4096
#define DD   1024
#define KNN  9

#define BLK_X 32               // sims blocks per batch (32*16 = 512, one wave @4/SM)
#define RPG   2                // rows per unit
#define UPW   8                // units per warp (8 warps * 8 units * 2 rows = 128 rows)
#define ROWS_PER_BLK 128
#define NCAND (BLK_X * KNN)    // 288 candidates per (b,k)

// -------- scratch (no device allocation allowed -> __device__ globals) ------
__device__ float2 g_cand[BB * KC * NCAND];   // (val, idx bits)  184 KB
__device__ float  g_invnorm[BB * NP];        // 1/||patch||      256 KB
__device__ int    g_top[BB * KC * KNN];      // winning indices
__device__ float  g_wsc[BB * KC * KNN];      // invnorm/9 of winners
__device__ unsigned g_count[BB];             // arrival counters (zero-init; reset in-kernel)

// ============================================================================
// Kernel 1: one pass over patches (268 MB -> memory bound) + first-level
// top-9 + (in the last-arriving block per batch) the global candidate merge
// via the threadfence-reduction pattern. Cue used RAW (positive row-scalar ->
// identical top-9 set; output only uses normalized patches).
// ============================================================================
__global__ void __launch_bounds__(256, 4) sims_kernel(const float* __restrict__ patches,
                                                      const float* __restrict__ cue) {
    const int b = blockIdx.y;
    const int bx = blockIdx.x;

    __shared__ float4 s_cue[KC * DD / 4];        // 20 KB (raw cue)
    __shared__ float  s_s[KC][ROWS_PER_BLK];     // 2.5 KB block-local cosines
    __shared__ unsigned s_arrived;
    {
        const float4* src = (const float4*)(cue + (size_t)b * KC * DD);
        for (int i = threadIdx.x; i < KC * DD / 4; i += 256) s_cue[i] = src[i];
    }
    __syncthreads();

    const int warp = threadIdx.x >> 5;
    const int lane = threadIdx.x & 31;
    const float4* pbase = (const float4*)(patches + (size_t)b * NP * DD);
    const int u0 = bx * (ROWS_PER_BLK / RPG);    // first unit of this block

    const float4* p = pbase + (size_t)(u0 + warp) * RPG * (DD / 4);
    float4 v0[RPG], v1[RPG], v2[RPG];
    #pragma unroll
    for (int rr = 0; rr < RPG; rr++) {
        v0[rr] = __ldcs(&p[lane + rr * (DD / 4)]);
        v1[rr] = __ldcs(&p[lane + 32 + rr * (DD / 4)]);
    }

    for (int m = 0; m < UPW; m++) {
        const bool has_next = (m < UPW - 1);
        const float4* pn = p + 8 * RPG * (DD / 4);    // next unit (stride 8)

        float acc[RPG][6];
        #pragma unroll
        for (int rr = 0; rr < RPG; rr++)
            #pragma unroll
            for (int i = 0; i < 6; i++) acc[rr][i] = 0.f;

        #pragma unroll
        for (int j = 0; j < 8; j++) {
            if (j < 6) {
                const int offn = lane + (j + 2) * 32;
                #pragma unroll
                for (int rr = 0; rr < RPG; rr++)
                    v2[rr] = __ldcs(&p[offn + rr * (DD / 4)]);
            } else if (has_next) {
                const int offn = lane + (j - 6) * 32;
                #pragma unroll
                for (int rr = 0; rr < RPG; rr++)
                    v2[rr] = __ldcs(&pn[offn + rr * (DD / 4)]);
            }

            const int off = lane + j * 32;
            #pragma unroll
            for (int rr = 0; rr < RPG; rr++) {
                acc[rr][5] = fmaf(v0[rr].x, v0[rr].x, acc[rr][5]);
                acc[rr][5] = fmaf(v0[rr].y, v0[rr].y, acc[rr][5]);
                acc[rr][5] = fmaf(v0[rr].z, v0[rr].z, acc[rr][5]);
                acc[rr][5] = fmaf(v0[rr].w, v0[rr].w, acc[rr][5]);
            }
            #pragma unroll
            for (int k = 0; k < KC; k++) {
                const float4 c = s_cue[k * (DD / 4) + off];
                #pragma unroll
                for (int rr = 0; rr < RPG; rr++) {
                    acc[rr][k] = fmaf(v0[rr].x, c.x, acc[rr][k]);
                    acc[rr][k] = fmaf(v0[rr].y, c.y, acc[rr][k]);
                    acc[rr][k] = fmaf(v0[rr].z, c.z, acc[rr][k]);
                    acc[rr][k] = fmaf(v0[rr].w, c.w, acc[rr][k]);
                }
            }
            #pragma unroll
            for (int rr = 0; rr < RPG; rr++) { v0[rr] = v1[rr]; v1[rr] = v2[rr]; }
        }

        const int lrow0 = (warp + m * 8) * RPG;
        #pragma unroll
        for (int rr = 0; rr < RPG; rr++) {
            #pragma unroll
            for (int i = 0; i < 6; i++)
                #pragma unroll
                for (int o = 16; o; o >>= 1)
                    acc[rr][i] += __shfl_xor_sync(0xffffffffu, acc[rr][i], o);
            const float inv = rsqrtf(fmaxf(acc[rr][5], 1e-24f));
            float val = acc[rr][0];
            if (lane == 1) val = acc[rr][1];
            if (lane == 2) val = acc[rr][2];
            if (lane == 3) val = acc[rr][3];
            if (lane == 4) val = acc[rr][4];
            if (lane < 5)
                s_s[lane][lrow0 + rr] = val * inv;
            else if (lane == 5)
                g_invnorm[(size_t)b * NP + bx * ROWS_PER_BLK + lrow0 + rr] = inv;
        }

        if (has_next) p = pn;
    }
    __syncthreads();

    // Block-local top-9 per cue: warp k (k<5) selects from s_s[k][0..128).
    if (warp < KC) {
        const int k = warp;
        float v4[4];
        const int base = lane * 4;
        #pragma unroll
        for (int i = 0; i < 4; i++) v4[i] = s_s[k][base + i];

        float2* cand = g_cand + ((size_t)(b * KC + k) * BLK_X + bx) * KNN;
        for (int it = 0; it < KNN; it++) {
            float bv = -CUDART_INF_F; int bi = ROWS_PER_BLK;
            #pragma unroll
            for (int i = 0; i < 4; i++)
                if (v4[i] > bv) { bv = v4[i]; bi = base + i; }   // lowest idx on tie
            #pragma unroll
            for (int o = 16; o; o >>= 1) {
                const float ov = __shfl_xor_sync(0xffffffffu, bv, o);
                const int   oi = __shfl_xor_sync(0xffffffffu, bi, o);
                if (ov > bv || (ov == bv && oi < bi)) { bv = ov; bi = oi; }
            }
            if ((bi >> 2) == lane) v4[bi & 3] = -CUDART_INF_F;   // mask winner
            if (lane == 0)
                cand[it] = make_float2(bv, __int_as_float(bx * ROWS_PER_BLK + bi));
        }
    }

    // ---- last-block-per-batch global merge (threadfence-reduction) --------
    __syncthreads();
    __threadfence();                          // release our cand/invnorm writes
    if (threadIdx.x == 0)
        s_arrived = atomicAdd(&g_count[b], 1u);
    __syncthreads();
    if (s_arrived != BLK_X - 1) return;
    __threadfence();                          // acquire other blocks' writes

    if (threadIdx.x == 0) g_count[b] = 0u;    // reset for next graph replay

    if (warp < KC) {
        const int k = warp;
        const float2* cand = g_cand + (size_t)(b * KC + k) * NCAND;
        // lane holds slots lane + s*32, s = 0..8 (288 candidates)
        float v[9]; int x[9];
        #pragma unroll
        for (int s = 0; s < 9; s++) {
            const float2 c = cand[lane + s * 32];
            v[s] = c.x; x[s] = __float_as_int(c.y);
        }
        for (int it = 0; it < KNN; it++) {
            float bv = -CUDART_INF_F; int bi = NP; int bs = 0;
            #pragma unroll
            for (int s = 0; s < 9; s++)
                if (v[s] > bv || (v[s] == bv && x[s] < bi)) { bv = v[s]; bi = x[s]; bs = s; }
            int blane = lane;
            #pragma unroll
            for (int o = 16; o; o >>= 1) {
                const float ov = __shfl_xor_sync(0xffffffffu, bv, o);
                const int   oi = __shfl_xor_sync(0xffffffffu, bi, o);
                const int   os = __shfl_xor_sync(0xffffffffu, bs, o);
                const int   ol = __shfl_xor_sync(0xffffffffu, blane, o);
                if (ov > bv || (ov == bv && oi < bi)) { bv = ov; bi = oi; bs = os; blane = ol; }
            }
            if (lane == blane) v[bs] = -CUDART_INF_F;            // mask winner
            if (lane == 0) {
                g_top[(b * KC + k) * KNN + it] = bi;
                g_wsc[(b * KC + k) * KNN + it] =
                    g_invnorm[(size_t)b * NP + bi] * (1.0f / (float)KNN);
            }
        }
    }
}

// ============================================================================
// Kernel 2: pure gather. grid = 80 blocks (one per (b,k)), 256 threads.
// out[b,k,:] = sum_i patches[b, top_i, :] * (invnorm_i / 9).
// ============================================================================
__global__ void __launch_bounds__(256) gather_kernel(const float* __restrict__ patches,
                                                     float* __restrict__ out) {
    const int bk = blockIdx.x;          // 0..79
    const int b = bk / KC;
    const int tid = threadIdx.x;

    __shared__ int   s_top[KNN];
    __shared__ float s_sc[KNN];
    if (tid < KNN) {
        s_top[tid] = g_top[bk * KNN + tid];
        s_sc[tid]  = g_wsc[bk * KNN + tid];
    }
    __syncthreads();

    float4 acc = make_float4(0.f, 0.f, 0.f, 0.f);
    #pragma unroll
    for (int i = 0; i < KNN; i++) {
        const float4* prow =
            (const float4*)(patches + ((size_t)b * NP + s_top[i]) * DD);
        const float4 v = prow[tid];
        const float sc = s_sc[i];
        acc.x = fmaf(v.x, sc, acc.x);
        acc.y = fmaf(v.y, sc, acc.y);
        acc.z = fmaf(v.z, sc, acc.z);
        acc.w = fmaf(v.w, sc, acc.w);
    }
    ((float4*)out)[(size_t)bk * (DD / 4) + tid] = acc;
}

// ============================================================================
extern "C" void kernel_launch(void* const* d_in, const int* in_sizes, int n_in,
                              void* d_out, int out_size) {
    const float* cue     = (const float*)d_in[0];
    const float* patches = (const float*)d_in[1];
    // defensive: identify by element count (cue = 81920, patches = 67108864)
    if (n_in >= 2 && in_sizes[0] > in_sizes[1]) {
        cue     = (const float*)d_in[1];
        patches = (const float*)d_in[0];
    }

    dim3 g1(BLK_X, BB);
    sims_kernel<<<g1, 256>>>(patches, cue);

    gather_kernel<<<BB * KC, 256>>>(patches, (float*)d_out);
}

// round 10
// speedup vs baseline: 1.1126x; 1.0985x over previous
#include <cuda_runtime.h>
#include <math_constants.h>

// Problem shape (fixed by the benchmark)
#define BB   16
#define KC   5
#define NP   4096
#define DD   1024
#define KNN  9

#define BLK_X 32               // sims blocks per batch (32*16 = 512, one wave @4/SM)
#define RPG   2                // rows per unit
#define UPW   8                // units per warp (8 warps * 8 units * 2 rows = 128 rows)
#define ROWS_PER_BLK 128
#define NCAND (BLK_X * KNN)    // 288 candidates per (b,k)

// -------- scratch (no device allocation allowed -> __device__ globals) ------
__device__ float2 g_cand[BB * KC * NCAND];  // (val, idx-as-float-bits) 184 KB
__device__ float  g_invnorm[BB * NP];       // 1/||patch||             256 KB

// ============================================================================
// Kernel 1 (identical to the proven R7 version): one pass over patches
// (268 MB streamed once -> memory bound) + first-level top-9 per 128-row
// partition. Cue used RAW (positive row-scalar -> identical top-9 set; the
// output only involves normalized patches).
// ============================================================================
__global__ void __launch_bounds__(256, 4) sims_kernel(const float* __restrict__ patches,
                                                      const float* __restrict__ cue) {
    const int b = blockIdx.y;
    const int bx = blockIdx.x;

    __shared__ float4 s_cue[KC * DD / 4];        // 20 KB (raw cue)
    __shared__ float  s_s[KC][ROWS_PER_BLK];     // 2.5 KB block-local cosines
    {
        const float4* src = (const float4*)(cue + (size_t)b * KC * DD);
        for (int i = threadIdx.x; i < KC * DD / 4; i += 256) s_cue[i] = src[i];
    }
    __syncthreads();

    const int warp = threadIdx.x >> 5;
    const int lane = threadIdx.x & 31;
    const float4* pbase = (const float4*)(patches + (size_t)b * NP * DD);
    const int u0 = bx * (ROWS_PER_BLK / RPG);    // first unit of this block

    const float4* p = pbase + (size_t)(u0 + warp) * RPG * (DD / 4);
    float4 v0[RPG], v1[RPG], v2[RPG];
    #pragma unroll
    for (int rr = 0; rr < RPG; rr++) {
        v0[rr] = __ldcs(&p[lane + rr * (DD / 4)]);
        v1[rr] = __ldcs(&p[lane + 32 + rr * (DD / 4)]);
    }

    for (int m = 0; m < UPW; m++) {
        const bool has_next = (m < UPW - 1);
        const float4* pn = p + 8 * RPG * (DD / 4);    // next unit (stride 8)

        float acc[RPG][6];
        #pragma unroll
        for (int rr = 0; rr < RPG; rr++)
            #pragma unroll
            for (int i = 0; i < 6; i++) acc[rr][i] = 0.f;

        #pragma unroll
        for (int j = 0; j < 8; j++) {
            if (j < 6) {
                const int offn = lane + (j + 2) * 32;
                #pragma unroll
                for (int rr = 0; rr < RPG; rr++)
                    v2[rr] = __ldcs(&p[offn + rr * (DD / 4)]);
            } else if (has_next) {
                const int offn = lane + (j - 6) * 32;
                #pragma unroll
                for (int rr = 0; rr < RPG; rr++)
                    v2[rr] = __ldcs(&pn[offn + rr * (DD / 4)]);
            }

            const int off = lane + j * 32;
            #pragma unroll
            for (int rr = 0; rr < RPG; rr++) {
                acc[rr][5] = fmaf(v0[rr].x, v0[rr].x, acc[rr][5]);
                acc[rr][5] = fmaf(v0[rr].y, v0[rr].y, acc[rr][5]);
                acc[rr][5] = fmaf(v0[rr].z, v0[rr].z, acc[rr][5]);
                acc[rr][5] = fmaf(v0[rr].w, v0[rr].w, acc[rr][5]);
            }
            #pragma unroll
            for (int k = 0; k < KC; k++) {
                const float4 c = s_cue[k * (DD / 4) + off];
                #pragma unroll
                for (int rr = 0; rr < RPG; rr++) {
                    acc[rr][k] = fmaf(v0[rr].x, c.x, acc[rr][k]);
                    acc[rr][k] = fmaf(v0[rr].y, c.y, acc[rr][k]);
                    acc[rr][k] = fmaf(v0[rr].z, c.z, acc[rr][k]);
                    acc[rr][k] = fmaf(v0[rr].w, c.w, acc[rr][k]);
                }
            }
            #pragma unroll
            for (int rr = 0; rr < RPG; rr++) { v0[rr] = v1[rr]; v1[rr] = v2[rr]; }
        }

        const int lrow0 = (warp + m * 8) * RPG;
        #pragma unroll
        for (int rr = 0; rr < RPG; rr++) {
            #pragma unroll
            for (int i = 0; i < 6; i++)
                #pragma unroll
                for (int o = 16; o; o >>= 1)
                    acc[rr][i] += __shfl_xor_sync(0xffffffffu, acc[rr][i], o);
            const float inv = rsqrtf(fmaxf(acc[rr][5], 1e-24f));
            float val = acc[rr][0];
            if (lane == 1) val = acc[rr][1];
            if (lane == 2) val = acc[rr][2];
            if (lane == 3) val = acc[rr][3];
            if (lane == 4) val = acc[rr][4];
            if (lane < 5)
                s_s[lane][lrow0 + rr] = val * inv;
            else if (lane == 5)
                g_invnorm[(size_t)b * NP + bx * ROWS_PER_BLK + lrow0 + rr] = inv;
        }

        if (has_next) p = pn;
    }
    __syncthreads();

    // Block-local top-9 per cue: warp k selects from s_s[k][0..128).
    if (warp < KC) {
        const int k = warp;
        float v4[4];
        const int base = lane * 4;
        #pragma unroll
        for (int i = 0; i < 4; i++) v4[i] = s_s[k][base + i];

        float2* cand = g_cand + ((size_t)(b * KC + k) * BLK_X + bx) * KNN;
        for (int it = 0; it < KNN; it++) {
            float bv = -CUDART_INF_F; int bi = ROWS_PER_BLK;
            #pragma unroll
            for (int i = 0; i < 4; i++)
                if (v4[i] > bv) { bv = v4[i]; bi = base + i; }   // lowest idx on tie
            #pragma unroll
            for (int o = 16; o; o >>= 1) {
                const float ov = __shfl_xor_sync(0xffffffffu, bv, o);
                const int   oi = __shfl_xor_sync(0xffffffffu, bi, o);
                if (ov > bv || (ov == bv && oi < bi)) { bv = ov; bi = oi; }
            }
            if ((bi >> 2) == lane) v4[bi & 3] = -CUDART_INF_F;   // mask winner
            if (lane == 0)
                cand[it] = make_float2(bv, __int_as_float(bx * ROWS_PER_BLK + bi));
        }
    }
}

// ============================================================================
// Kernel 2: per (b,k): merge 288 candidates -> global top-9, then gather with
// ALL 32 warps (1024 threads): group g = tid>>8 handles rows {g, g+4} (+row 8
// for g==0), partial sums combined through smem. grid = 80 blocks.
// ============================================================================
__global__ void __launch_bounds__(1024) topk_kernel(const float* __restrict__ patches,
                                                    float* __restrict__ out) {
    const int bk = blockIdx.x;          // 0..79
    const int b = bk / KC;
    const int tid = threadIdx.x;

    __shared__ float  s_v[NCAND];
    __shared__ int    s_i[NCAND];
    __shared__ int    s_top[KNN];
    __shared__ float  s_inv[KNN];
    __shared__ float4 s_part[3][DD / 4];   // 12 KB partials (groups 1..3)

    const float2* cand = g_cand + (size_t)bk * NCAND;
    if (tid < NCAND) {
        const float2 c = cand[tid];
        s_v[tid] = c.x;
        s_i[tid] = __float_as_int(c.y);
    }
    __syncthreads();

    if (tid < 32) {
        const int lane = tid;
        // lane holds slots lane + s*32, s = 0..8 (register resident)
        float v[9]; int x[9];
        #pragma unroll
        for (int s = 0; s < 9; s++) {
            const int g = lane + s * 32;
            v[s] = s_v[g]; x[s] = s_i[g];
        }
        for (int it = 0; it < KNN; it++) {
            float bv = -CUDART_INF_F; int bi = NP; int bs = 0;
            #pragma unroll
            for (int s = 0; s < 9; s++)
                if (v[s] > bv || (v[s] == bv && x[s] < bi)) { bv = v[s]; bi = x[s]; bs = s; }
            int blane = lane;
            #pragma unroll
            for (int o = 16; o; o >>= 1) {
                const float ov = __shfl_xor_sync(0xffffffffu, bv, o);
                const int   oi = __shfl_xor_sync(0xffffffffu, bi, o);
                const int   os = __shfl_xor_sync(0xffffffffu, bs, o);
                const int   ol = __shfl_xor_sync(0xffffffffu, blane, o);
                if (ov > bv || (ov == bv && oi < bi)) { bv = ov; bi = oi; bs = os; blane = ol; }
            }
            if (lane == blane) v[bs] = -CUDART_INF_F;          // mask winner
            if (lane == 0) s_top[it] = bi;
        }
        if (lane < KNN)
            s_inv[lane] = g_invnorm[(size_t)b * NP + s_top[lane]] * (1.0f / (float)KNN);
    }
    __syncthreads();

    // Parallel gather: group g (0..3) does rows g, g+4 (+ row 8 for g==0).
    const int grp = tid >> 8;           // 0..3
    const int c   = tid & 255;          // float4 index within the D row

    float4 acc = make_float4(0.f, 0.f, 0.f, 0.f);
    #pragma unroll
    for (int s = 0; s < 2; s++) {
        const int i = grp + s * 4;      // rows 0..7 across groups
        const float4 v = ((const float4*)(patches + ((size_t)b * NP + s_top[i]) * DD))[c];
        const float sc = s_inv[i];
        acc.x = fmaf(v.x, sc, acc.x);
        acc.y = fmaf(v.y, sc, acc.y);
        acc.z = fmaf(v.z, sc, acc.z);
        acc.w = fmaf(v.w, sc, acc.w);
    }
    if (grp == 0) {                     // row 8
        const float4 v = ((const float4*)(patches + ((size_t)b * NP + s_top[8]) * DD))[c];
        const float sc = s_inv[8];
        acc.x = fmaf(v.x, sc, acc.x);
        acc.y = fmaf(v.y, sc, acc.y);
        acc.z = fmaf(v.z, sc, acc.z);
        acc.w = fmaf(v.w, sc, acc.w);
    }

    if (grp != 0) s_part[grp - 1][c] = acc;
    __syncthreads();

    if (grp == 0) {
        #pragma unroll
        for (int g2 = 0; g2 < 3; g2++) {
            const float4 pz = s_part[g2][c];
            acc.x += pz.x; acc.y += pz.y; acc.z += pz.z; acc.w += pz.w;
        }
        ((float4*)out)[(size_t)bk * (DD / 4) + c] = acc;
    }
}

// ============================================================================
extern "C" void kernel_launch(void* const* d_in, const int* in_sizes, int n_in,
                              void* d_out, int out_size) {
    const float* cue     = (const float*)d_in[0];
    const float* patches = (const float*)d_in[1];
    // defensive: identify by element count (cue = 81920, patches = 67108864)
    if (n_in >= 2 && in_sizes[0] > in_sizes[1]) {
        cue     = (const float*)d_in[1];
        patches = (const float*)d_in[0];
    }

    dim3 g1(BLK_X, BB);
    sims_kernel<<<g1, 256>>>(patches, cue);

    topk_kernel<<<BB * KC, 1024>>>(patches, (float*)d_out);
}

// round 11
// speedup vs baseline: 1.1178x; 1.0047x over previous
#include <cuda_runtime.h>
#include <math_constants.h>

// Problem shape (fixed by the benchmark)
#define BB   16
#define KC   5
#define NP   4096
#define DD   1024
#define KNN  9

#define BLK_X 32               // sims blocks per batch (32*16 = 512, one wave @4/SM)
#define RPG   2                // rows per unit
#define UPW   8                // units per warp (8 warps * 8 units * 2 rows = 128 rows)
#define ROWS_PER_BLK 128
#define NCAND (BLK_X * KNN)    // 288 candidates per (b,k)
#define QD    4                // D-quarters in the gather kernel

// -------- scratch (no device allocation allowed -> __device__ globals) ------
__device__ float2 g_cand[BB * KC * NCAND];  // (val, idx-as-float-bits) 184 KB
__device__ float  g_invnorm[BB * NP];       // 1/||patch||             256 KB

// ============================================================================
// Kernel 1 (identical to the proven R7 version): one pass over patches
// (268 MB streamed once -> memory bound) + first-level top-9 per 128-row
// partition. Cue used RAW (positive row-scalar -> identical top-9 set; the
// output only involves normalized patches).
// ============================================================================
__global__ void __launch_bounds__(256, 4) sims_kernel(const float* __restrict__ patches,
                                                      const float* __restrict__ cue) {
    const int b = blockIdx.y;
    const int bx = blockIdx.x;

    __shared__ float4 s_cue[KC * DD / 4];        // 20 KB (raw cue)
    __shared__ float  s_s[KC][ROWS_PER_BLK];     // 2.5 KB block-local cosines
    {
        const float4* src = (const float4*)(cue + (size_t)b * KC * DD);
        for (int i = threadIdx.x; i < KC * DD / 4; i += 256) s_cue[i] = src[i];
    }
    __syncthreads();

    const int warp = threadIdx.x >> 5;
    const int lane = threadIdx.x & 31;
    const float4* pbase = (const float4*)(patches + (size_t)b * NP * DD);
    const int u0 = bx * (ROWS_PER_BLK / RPG);    // first unit of this block

    const float4* p = pbase + (size_t)(u0 + warp) * RPG * (DD / 4);
    float4 v0[RPG], v1[RPG], v2[RPG];
    #pragma unroll
    for (int rr = 0; rr < RPG; rr++) {
        v0[rr] = __ldcs(&p[lane + rr * (DD / 4)]);
        v1[rr] = __ldcs(&p[lane + 32 + rr * (DD / 4)]);
    }

    for (int m = 0; m < UPW; m++) {
        const bool has_next = (m < UPW - 1);
        const float4* pn = p + 8 * RPG * (DD / 4);    // next unit (stride 8)

        float acc[RPG][6];
        #pragma unroll
        for (int rr = 0; rr < RPG; rr++)
            #pragma unroll
            for (int i = 0; i < 6; i++) acc[rr][i] = 0.f;

        #pragma unroll
        for (int j = 0; j < 8; j++) {
            if (j < 6) {
                const int offn = lane + (j + 2) * 32;
                #pragma unroll
                for (int rr = 0; rr < RPG; rr++)
                    v2[rr] = __ldcs(&p[offn + rr * (DD / 4)]);
            } else if (has_next) {
                const int offn = lane + (j - 6) * 32;
                #pragma unroll
                for (int rr = 0; rr < RPG; rr++)
                    v2[rr] = __ldcs(&pn[offn + rr * (DD / 4)]);
            }

            const int off = lane + j * 32;
            #pragma unroll
            for (int rr = 0; rr < RPG; rr++) {
                acc[rr][5] = fmaf(v0[rr].x, v0[rr].x, acc[rr][5]);
                acc[rr][5] = fmaf(v0[rr].y, v0[rr].y, acc[rr][5]);
                acc[rr][5] = fmaf(v0[rr].z, v0[rr].z, acc[rr][5]);
                acc[rr][5] = fmaf(v0[rr].w, v0[rr].w, acc[rr][5]);
            }
            #pragma unroll
            for (int k = 0; k < KC; k++) {
                const float4 c = s_cue[k * (DD / 4) + off];
                #pragma unroll
                for (int rr = 0; rr < RPG; rr++) {
                    acc[rr][k] = fmaf(v0[rr].x, c.x, acc[rr][k]);
                    acc[rr][k] = fmaf(v0[rr].y, c.y, acc[rr][k]);
                    acc[rr][k] = fmaf(v0[rr].z, c.z, acc[rr][k]);
                    acc[rr][k] = fmaf(v0[rr].w, c.w, acc[rr][k]);
                }
            }
            #pragma unroll
            for (int rr = 0; rr < RPG; rr++) { v0[rr] = v1[rr]; v1[rr] = v2[rr]; }
        }

        const int lrow0 = (warp + m * 8) * RPG;
        #pragma unroll
        for (int rr = 0; rr < RPG; rr++) {
            #pragma unroll
            for (int i = 0; i < 6; i++)
                #pragma unroll
                for (int o = 16; o; o >>= 1)
                    acc[rr][i] += __shfl_xor_sync(0xffffffffu, acc[rr][i], o);
            const float inv = rsqrtf(fmaxf(acc[rr][5], 1e-24f));
            float val = acc[rr][0];
            if (lane == 1) val = acc[rr][1];
            if (lane == 2) val = acc[rr][2];
            if (lane == 3) val = acc[rr][3];
            if (lane == 4) val = acc[rr][4];
            if (lane < 5)
                s_s[lane][lrow0 + rr] = val * inv;
            else if (lane == 5)
                g_invnorm[(size_t)b * NP + bx * ROWS_PER_BLK + lrow0 + rr] = inv;
        }

        if (has_next) p = pn;
    }
    __syncthreads();

    // Block-local top-9 per cue: warp k selects from s_s[k][0..128).
    if (warp < KC) {
        const int k = warp;
        float v4[4];
        const int base = lane * 4;
        #pragma unroll
        for (int i = 0; i < 4; i++) v4[i] = s_s[k][base + i];

        float2* cand = g_cand + ((size_t)(b * KC + k) * BLK_X + bx) * KNN;
        for (int it = 0; it < KNN; it++) {
            float bv = -CUDART_INF_F; int bi = ROWS_PER_BLK;
            #pragma unroll
            for (int i = 0; i < 4; i++)
                if (v4[i] > bv) { bv = v4[i]; bi = base + i; }   // lowest idx on tie
            #pragma unroll
            for (int o = 16; o; o >>= 1) {
                const float ov = __shfl_xor_sync(0xffffffffu, bv, o);
                const int   oi = __shfl_xor_sync(0xffffffffu, bi, o);
                if (ov > bv || (ov == bv && oi < bi)) { bv = ov; bi = oi; }
            }
            if ((bi >> 2) == lane) v4[bi & 3] = -CUDART_INF_F;   // mask winner
            if (lane == 0)
                cand[it] = make_float2(bv, __int_as_float(bx * ROWS_PER_BLK + bi));
        }
    }
}

// ============================================================================
// Kernel 2: grid (QD, 80). Each block REDUNDANTLY merges the 288 candidates
// of its (b,k) (deterministic), then gathers its quarter of D (9 quarter-rows
// = 9 KB). 320 blocks: merge latency overlaps across blocks; no long serial
// chain dominates.
// ============================================================================
__global__ void __launch_bounds__(256) topk_kernel(const float* __restrict__ patches,
                                                   float* __restrict__ out) {
    const int q  = blockIdx.x;          // 0..3 D-quarter
    const int bk = blockIdx.y;          // 0..79
    const int b = bk / KC;
    const int tid = threadIdx.x;

    __shared__ float  s_v[NCAND];
    __shared__ int    s_i[NCAND];
    __shared__ int    s_top[KNN];
    __shared__ float  s_inv[KNN];
    __shared__ float4 s_part[3][DD / 4 / QD];   // 3 KB partials (groups 1..3)

    const float2* cand = g_cand + (size_t)bk * NCAND;
    for (int t = tid; t < NCAND; t += 256) {
        const float2 c = cand[t];
        s_v[t] = c.x;
        s_i[t] = __float_as_int(c.y);
    }
    __syncthreads();

    if (tid < 32) {
        const int lane = tid;
        float v[9]; int x[9];
        #pragma unroll
        for (int s = 0; s < 9; s++) {
            const int g = lane + s * 32;
            v[s] = s_v[g]; x[s] = s_i[g];
        }
        for (int it = 0; it < KNN; it++) {
            float bv = -CUDART_INF_F; int bi = NP; int bs = 0;
            #pragma unroll
            for (int s = 0; s < 9; s++)
                if (v[s] > bv || (v[s] == bv && x[s] < bi)) { bv = v[s]; bi = x[s]; bs = s; }
            int blane = lane;
            #pragma unroll
            for (int o = 16; o; o >>= 1) {
                const float ov = __shfl_xor_sync(0xffffffffu, bv, o);
                const int   oi = __shfl_xor_sync(0xffffffffu, bi, o);
                const int   os = __shfl_xor_sync(0xffffffffu, bs, o);
                const int   ol = __shfl_xor_sync(0xffffffffu, blane, o);
                if (ov > bv || (ov == bv && oi < bi)) { bv = ov; bi = oi; bs = os; blane = ol; }
            }
            if (lane == blane) v[bs] = -CUDART_INF_F;          // mask winner
            if (lane == 0) s_top[it] = bi;
        }
        if (lane < KNN)
            s_inv[lane] = g_invnorm[(size_t)b * NP + s_top[lane]] * (1.0f / (float)KNN);
    }
    __syncthreads();

    // Gather this block's quarter: 64 float4 columns. Group g = tid>>6 does
    // rows g, g+4 (+ row 8 for g==0); combine through smem.
    const int grp = tid >> 6;                    // 0..3
    const int cc  = tid & 63;                    // column within quarter
    const int col = q * (DD / 4 / QD) + cc;      // global float4 column

    float4 acc = make_float4(0.f, 0.f, 0.f, 0.f);
    #pragma unroll
    for (int s = 0; s < 2; s++) {
        const int i = grp + s * 4;               // rows 0..7 across groups
        const float4 v = ((const float4*)(patches + ((size_t)b * NP + s_top[i]) * DD))[col];
        const float sc = s_inv[i];
        acc.x = fmaf(v.x, sc, acc.x);
        acc.y = fmaf(v.y, sc, acc.y);
        acc.z = fmaf(v.z, sc, acc.z);
        acc.w = fmaf(v.w, sc, acc.w);
    }
    if (grp == 0) {                              // row 8
        const float4 v = ((const float4*)(patches + ((size_t)b * NP + s_top[8]) * DD))[col];
        const float sc = s_inv[8];
        acc.x = fmaf(v.x, sc, acc.x);
        acc.y = fmaf(v.y, sc, acc.y);
        acc.z = fmaf(v.z, sc, acc.z);
        acc.w = fmaf(v.w, sc, acc.w);
    }

    if (grp != 0) s_part[grp - 1][cc] = acc;
    __syncthreads();

    if (grp == 0) {
        #pragma unroll
        for (int g2 = 0; g2 < 3; g2++) {
            const float4 pz = s_part[g2][cc];
            acc.x += pz.x; acc.y += pz.y; acc.z += pz.z; acc.w += pz.w;
        }
        ((float4*)out)[(size_t)bk * (DD / 4) + col] = acc;
    }
}

// ============================================================================
extern "C" void kernel_launch(void* const* d_in, const int* in_sizes, int n_in,
                              void* d_out, int out_size) {
    const float* cue     = (const float*)d_in[0];
    const float* patches = (const float*)d_in[1];
    // defensive: identify by element count (cue = 81920, patches = 67108864)
    if (n_in >= 2 && in_sizes[0] > in_sizes[1]) {
        cue     = (const float*)d_in[1];
        patches = (const float*)d_in[0];
    }

    dim3 g1(BLK_X, BB);
    sims_kernel<<<g1, 256>>>(patches, cue);

    dim3 g2(QD, BB * KC);
    topk_kernel<<<g2, 256>>>(patches, (float*)d_out);
}